// round 1
// baseline (speedup 1.0000x reference)
#include <cuda_runtime.h>

// Problem constants
constexpr int kB = 512;   // batch
constexpr int kL = 128;   // seq len
constexpr int kD = 128;   // model dim
// H = 4 heads of 32

// Scratch (device globals: allocation-free rule)
__device__ float g_x [kB * kL * kD];                 // residual stream, [b][t][d]   (32 MB)
__device__ float g_xn[kB * kL * kD];                 // layernormed,    [b*L+l][d]   (32 MB)
__device__ float g_pre[(size_t)kL * kB * 4 * kD];    // gate preacts,   [t][b][g][d] (128 MB)

// ---------------------------------------------------------------------------
// Embedding gather: g_x[b,l,:] = emb[ids[b,l], :]
// ---------------------------------------------------------------------------
__global__ void k_embed(const int* __restrict__ ids, const float4* __restrict__ emb) {
    int tid = blockIdx.x * 256 + threadIdx.x;          // one float4 per thread
    if (tid >= kB * kL * 32) return;
    int row = tid >> 5;                                 // (b*L + l)
    int c4  = tid & 31;
    int id  = __ldg(&ids[row]);
    ((float4*)g_x)[tid] = emb[(size_t)id * 32 + c4];
}

// ---------------------------------------------------------------------------
// LayerNorm: one warp per row of 128
// ---------------------------------------------------------------------------
__global__ void k_ln(const float* __restrict__ w, const float* __restrict__ bb) {
    int t    = blockIdx.x * 256 + threadIdx.x;
    int warp = t >> 5;
    int lane = t & 31;
    float4 v = ((const float4*)g_x)[(size_t)warp * 32 + lane];
    float s = v.x + v.y + v.z + v.w;
    float q = v.x*v.x + v.y*v.y + v.z*v.z + v.w*v.w;
    #pragma unroll
    for (int o = 16; o; o >>= 1) {
        s += __shfl_xor_sync(0xffffffffu, s, o);
        q += __shfl_xor_sync(0xffffffffu, q, o);
    }
    float mu  = s * (1.f / 128.f);
    float var = fmaxf(q * (1.f / 128.f) - mu * mu, 0.f);
    float rs  = rsqrtf(var + 1e-5f);
    float4 wv = ((const float4*)w)[lane];
    float4 bv = ((const float4*)bb)[lane];
    float4 o4;
    o4.x = (v.x - mu) * rs * wv.x + bv.x;
    o4.y = (v.y - mu) * rs * wv.y + bv.y;
    o4.z = (v.z - mu) * rs * wv.z + bv.z;
    o4.w = (v.w - mu) * rs * wv.w + bv.w;
    ((float4*)g_xn)[(size_t)warp * 32 + lane] = o4;
}

// ---------------------------------------------------------------------------
// tf32 GEMM: pre[l,b,g*128+o] = xn[b*L+l, :] . W[g*128+o, :] + bias
// Block tile 128x128, 8 warps (2x4), warp tile 64x32, mma.m16n8k8.tf32
// ---------------------------------------------------------------------------
__device__ __forceinline__ unsigned to_tf32(float f) {
    unsigned u;
    asm("cvt.rna.tf32.f32 %0, %1;" : "=r"(u) : "f"(f));
    return u;
}

__global__ void __launch_bounds__(256) k_gemm(const float* __restrict__ W,
                                              const float* __restrict__ bias) {
    constexpr int STR = 132;                 // padded smem stride (floats)
    extern __shared__ unsigned sh[];
    unsigned* As = sh;                       // [128][132] tf32 of xn tile
    unsigned* Bs = sh + 128 * STR;           // [128][132] tf32 of W tile

    int tid = threadIdx.x;
    int bm  = blockIdx.x;                    // row tile (== batch index b)
    int bn  = blockIdx.y;                    // col tile (128 of 512)

    const float4* Ag = ((const float4*)g_xn) + (size_t)bm * 128 * 32;
    const float4* Wg = ((const float4*)W)    + (size_t)bn * 128 * 32;

    #pragma unroll
    for (int i = 0; i < 16; i++) {
        int e  = i * 256 + tid;              // float4 index within 128x32
        int r  = e >> 5, c4 = e & 31;
        float4 va = Ag[(size_t)r * 32 + c4];
        uint4 ua = make_uint4(to_tf32(va.x), to_tf32(va.y), to_tf32(va.z), to_tf32(va.w));
        *(uint4*)&As[r * STR + c4 * 4] = ua;
        float4 vb = Wg[(size_t)r * 32 + c4];
        uint4 ub = make_uint4(to_tf32(vb.x), to_tf32(vb.y), to_tf32(vb.z), to_tf32(vb.w));
        *(uint4*)&Bs[r * STR + c4 * 4] = ub;
    }
    __syncthreads();

    int warp = tid >> 5, lane = tid & 31;
    int wm = warp >> 2, wn = warp & 3;       // 2 x 4 warp grid
    int gid = lane >> 2, tg = lane & 3;

    float acc[4][4][4];
    #pragma unroll
    for (int i = 0; i < 4; i++)
        #pragma unroll
        for (int j = 0; j < 4; j++)
            #pragma unroll
            for (int c = 0; c < 4; c++) acc[i][j][c] = 0.f;

    #pragma unroll
    for (int ks = 0; ks < 16; ks++) {
        int k0 = ks * 8 + tg;
        unsigned a[4][4], bf[4][2];
        #pragma unroll
        for (int i = 0; i < 4; i++) {
            int r0 = wm * 64 + i * 16 + gid;
            a[i][0] = As[r0 * STR + k0];
            a[i][1] = As[(r0 + 8) * STR + k0];
            a[i][2] = As[r0 * STR + k0 + 4];
            a[i][3] = As[(r0 + 8) * STR + k0 + 4];
        }
        #pragma unroll
        for (int j = 0; j < 4; j++) {
            int n0 = wn * 32 + j * 8 + gid;
            bf[j][0] = Bs[n0 * STR + k0];
            bf[j][1] = Bs[n0 * STR + k0 + 4];
        }
        #pragma unroll
        for (int i = 0; i < 4; i++)
            #pragma unroll
            for (int j = 0; j < 4; j++)
                asm volatile(
                    "mma.sync.aligned.m16n8k8.row.col.f32.tf32.tf32.f32 "
                    "{%0,%1,%2,%3}, {%4,%5,%6,%7}, {%8,%9}, {%0,%1,%2,%3};"
                    : "+f"(acc[i][j][0]), "+f"(acc[i][j][1]),
                      "+f"(acc[i][j][2]), "+f"(acc[i][j][3])
                    : "r"(a[i][0]), "r"(a[i][1]), "r"(a[i][2]), "r"(a[i][3]),
                      "r"(bf[j][0]), "r"(bf[j][1]));
    }

    // epilogue: row r = b*128 + l  ->  pre[(l*512 + b)*512 + col], + bias
    #pragma unroll
    for (int i = 0; i < 4; i++) {
        int r0 = bm * 128 + wm * 64 + i * 16 + gid;
        int ra = r0, rb = r0 + 8;
        float* outa = g_pre + ((size_t)(ra & 127) * 512 + (ra >> 7)) * 512;
        float* outb = g_pre + ((size_t)(rb & 127) * 512 + (rb >> 7)) * 512;
        #pragma unroll
        for (int j = 0; j < 4; j++) {
            int col = bn * 128 + wn * 32 + j * 8 + tg * 2;
            float bz0 = __ldg(&bias[col]);
            float bz1 = __ldg(&bias[col + 1]);
            *(float2*)&outa[col] = make_float2(acc[i][j][0] + bz0, acc[i][j][1] + bz1);
            *(float2*)&outb[col] = make_float2(acc[i][j][2] + bz0, acc[i][j][3] + bz1);
        }
    }
}

// ---------------------------------------------------------------------------
// Recurrent sLSTM scan + fused GroupNorm + residual into g_x.
// One CTA per batch element, 128 threads (thread = dim d, warp = head).
// R (4 gates x 32 inputs) held in 128 registers per thread; h broadcast
// via warp shuffles. No barriers inside the 128-step loop.
// ---------------------------------------------------------------------------
__global__ void __launch_bounds__(128) k_scan(const float* __restrict__ R,
                                              const float* __restrict__ gnw) {
    int b    = blockIdx.x;
    int o    = threadIdx.x;
    int hh   = o >> 5;
    int lane = o & 31;

    // Rr[g*32 + d] = R[g][hh][d][lane]
    float Rr[128];
    #pragma unroll
    for (int g = 0; g < 4; g++)
        #pragma unroll
        for (int d = 0; d < 32; d++)
            Rr[g * 32 + d] = __ldg(&R[((g * 4 + hh) * 32 + d) * 32 + lane]);

    float gw = __ldg(&gnw[o]);

    float h = 0.f, c = 0.f, n = 0.f, m = 0.f;
    const float* pb = g_pre + (size_t)b * 512 + o;
    float* xb = g_x + (size_t)b * kL * kD + o;

    // prefetch step 0
    float p0 = pb[0], p1 = pb[128], p2 = pb[256], p3 = pb[384];

    for (int t = 0; t < kL; t++) {
        float ai = p0, af = p1, az = p2, ao = p3;
        if (t + 1 < kL) {
            const float* pn = pb + (size_t)(t + 1) * (kB * 512);
            p0 = pn[0]; p1 = pn[128]; p2 = pn[256]; p3 = pn[384];
        }
        // recurrent mix: within-head matvec via warp shuffles
        #pragma unroll
        for (int d = 0; d < 32; d++) {
            float hd = __shfl_sync(0xffffffffu, h, d);
            ai = fmaf(hd, Rr[d],      ai);
            af = fmaf(hd, Rr[32 + d], af);
            az = fmaf(hd, Rr[64 + d], az);
            ao = fmaf(hd, Rr[96 + d], ao);
        }
        // gate math
        float mn = fmaxf(af + m, ai);
        float iv = __expf(ai - mn);
        float fv = __expf(af + m - mn);
        c = fv * c + iv * tanhf(az);
        n = fv * n + iv;
        float sig = 1.f / (1.f + __expf(-ao));
        h = sig * c / n;
        m = mn;

        // fused GroupNorm over the head (this warp) + residual into g_x
        float s = h, q = h * h;
        #pragma unroll
        for (int off = 16; off; off >>= 1) {
            s += __shfl_xor_sync(0xffffffffu, s, off);
            q += __shfl_xor_sync(0xffffffffu, q, off);
        }
        float mu  = s * (1.f / 32.f);
        float var = fmaxf(q * (1.f / 32.f) - mu * mu, 0.f);
        float y   = (h - mu) * rsqrtf(var + 1e-5f) * gw;
        xb[(size_t)t * kD] += y;
    }
}

// ---------------------------------------------------------------------------
// Head: mean over time, then 128->64 ReLU MLP, then 64->2
// ---------------------------------------------------------------------------
__global__ void k_head(const float* __restrict__ w1, const float* __restrict__ b1,
                       const float* __restrict__ w2, const float* __restrict__ b2,
                       float* __restrict__ out) {
    __shared__ float pooled[128];
    __shared__ float hid[64];
    int b = blockIdx.x, o = threadIdx.x;
    const float* xb = g_x + (size_t)b * kL * kD + o;
    float s = 0.f;
    #pragma unroll 8
    for (int t = 0; t < kL; t++) s += xb[(size_t)t * kD];
    pooled[o] = s * (1.f / 128.f);
    __syncthreads();
    if (o < 64) {
        float a = __ldg(&b1[o]);
        const float* wr = w1 + o * 128;
        #pragma unroll
        for (int d = 0; d < 128; d++) a = fmaf(pooled[d], __ldg(&wr[d]), a);
        hid[o] = fmaxf(a, 0.f);
    }
    __syncthreads();
    if (o < 2) {
        float a = __ldg(&b2[o]);
        const float* wr = w2 + o * 64;
        #pragma unroll
        for (int j = 0; j < 64; j++) a = fmaf(hid[j], __ldg(&wr[j]), a);
        out[b * 2 + o] = a;
    }
}

// ---------------------------------------------------------------------------
extern "C" void kernel_launch(void* const* d_in, const int* in_sizes, int n_in,
                              void* d_out, int out_size) {
    const int*   ids  = (const int*)  d_in[0];
    const float* emb  = (const float*)d_in[1];
    const float* ln_w = (const float*)d_in[2];
    const float* ln_b = (const float*)d_in[3];
    const float* Wg   = (const float*)d_in[4];
    const float* Rg   = (const float*)d_in[5];
    const float* bg   = (const float*)d_in[6];
    const float* gn_w = (const float*)d_in[7];
    const float* w1   = (const float*)d_in[8];
    const float* b1   = (const float*)d_in[9];
    const float* w2   = (const float*)d_in[10];
    const float* b2   = (const float*)d_in[11];
    float* out = (float*)d_out;

    constexpr int GEMM_SMEM = 2 * 128 * 132 * 4;   // 135168 B
    cudaFuncSetAttribute(k_gemm, cudaFuncAttributeMaxDynamicSharedMemorySize, GEMM_SMEM);

    k_embed<<<(kB * kL * 32 + 255) / 256, 256>>>(ids, (const float4*)emb);
    for (int l = 0; l < 2; l++) {
        k_ln<<<kB * kL / 8, 256>>>(ln_w + l * 128, ln_b + l * 128);
        k_gemm<<<dim3(512, 4), 256, GEMM_SMEM>>>(Wg + (size_t)l * 4 * 128 * 128,
                                                 bg + l * 512);
        k_scan<<<512, 128>>>(Rg + (size_t)l * 4 * 4 * 32 * 32, gn_w + l * 128);
    }
    k_head<<<512, 128>>>(w1, b1, w2, b2, out);
}

// round 2
// speedup vs baseline: 1.3322x; 1.3322x over previous
#include <cuda_runtime.h>

// Problem constants
constexpr int kB = 512;   // batch
constexpr int kL = 128;   // seq len
constexpr int kD = 128;   // model dim
// H = 4 heads of 32

// Scratch (device globals: allocation-free rule)
__device__ float g_x [kB * kL * kD];                 // residual stream, [b][t][d]   (32 MB)
__device__ float g_xn[kB * kL * kD];                 // layernormed,    [b*L+l][d]   (32 MB)
__device__ float g_pre[(size_t)kL * kB * 4 * kD];    // gate preacts,   [t][b][g][d] (128 MB)

typedef unsigned long long ull;

__device__ __forceinline__ ull pack2(float lo, float hi) {
    ull r; asm("mov.b64 %0,{%1,%2};" : "=l"(r) : "f"(lo), "f"(hi)); return r;
}
__device__ __forceinline__ void unpack2(ull v, float& lo, float& hi) {
    asm("mov.b64 {%0,%1},%2;" : "=f"(lo), "=f"(hi) : "l"(v));
}
__device__ __forceinline__ ull ffma2(ull a, ull b, ull c) {
    ull d; asm("fma.rn.f32x2 %0,%1,%2,%3;" : "=l"(d) : "l"(a), "l"(b), "l"(c)); return d;
}
__device__ __forceinline__ ull add2(ull a, ull b) {
    ull d; asm("add.rn.f32x2 %0,%1,%2;" : "=l"(d) : "l"(a), "l"(b)); return d;
}

// ---------------------------------------------------------------------------
// Embedding gather: g_x[b,l,:] = emb[ids[b,l], :]
// ---------------------------------------------------------------------------
__global__ void k_embed(const int* __restrict__ ids, const float4* __restrict__ emb) {
    int tid = blockIdx.x * 256 + threadIdx.x;          // one float4 per thread
    if (tid >= kB * kL * 32) return;
    int row = tid >> 5;                                 // (b*L + l)
    int c4  = tid & 31;
    int id  = __ldg(&ids[row]);
    ((float4*)g_x)[tid] = emb[(size_t)id * 32 + c4];
}

// ---------------------------------------------------------------------------
// LayerNorm: one warp per row of 128
// ---------------------------------------------------------------------------
__global__ void k_ln(const float* __restrict__ w, const float* __restrict__ bb) {
    int t    = blockIdx.x * 256 + threadIdx.x;
    int warp = t >> 5;
    int lane = t & 31;
    float4 v = ((const float4*)g_x)[(size_t)warp * 32 + lane];
    float s = v.x + v.y + v.z + v.w;
    float q = v.x*v.x + v.y*v.y + v.z*v.z + v.w*v.w;
    #pragma unroll
    for (int o = 16; o; o >>= 1) {
        s += __shfl_xor_sync(0xffffffffu, s, o);
        q += __shfl_xor_sync(0xffffffffu, q, o);
    }
    float mu  = s * (1.f / 128.f);
    float var = fmaxf(q * (1.f / 128.f) - mu * mu, 0.f);
    float rs  = rsqrtf(var + 1e-5f);
    float4 wv = ((const float4*)w)[lane];
    float4 bv = ((const float4*)bb)[lane];
    float4 o4;
    o4.x = (v.x - mu) * rs * wv.x + bv.x;
    o4.y = (v.y - mu) * rs * wv.y + bv.y;
    o4.z = (v.z - mu) * rs * wv.z + bv.z;
    o4.w = (v.w - mu) * rs * wv.w + bv.w;
    ((float4*)g_xn)[(size_t)warp * 32 + lane] = o4;
}

// ---------------------------------------------------------------------------
// tf32 GEMM: pre[l,b,g*128+o] = xn[b*L+l, :] . W[g*128+o, :] + bias
// Block tile 128x128, 8 warps (2x4), warp tile 64x32, mma.m16n8k8.tf32
// ---------------------------------------------------------------------------
__device__ __forceinline__ unsigned to_tf32(float f) {
    unsigned u;
    asm("cvt.rna.tf32.f32 %0, %1;" : "=r"(u) : "f"(f));
    return u;
}

__global__ void __launch_bounds__(256) k_gemm(const float* __restrict__ W,
                                              const float* __restrict__ bias) {
    constexpr int STR = 132;                 // padded smem stride (floats)
    extern __shared__ unsigned sh[];
    unsigned* As = sh;                       // [128][132] tf32 of xn tile
    unsigned* Bs = sh + 128 * STR;           // [128][132] tf32 of W tile

    int tid = threadIdx.x;
    int bm  = blockIdx.x;                    // row tile (== batch index b)
    int bn  = blockIdx.y;                    // col tile (128 of 512)

    const float4* Ag = ((const float4*)g_xn) + (size_t)bm * 128 * 32;
    const float4* Wg = ((const float4*)W)    + (size_t)bn * 128 * 32;

    #pragma unroll
    for (int i = 0; i < 16; i++) {
        int e  = i * 256 + tid;              // float4 index within 128x32
        int r  = e >> 5, c4 = e & 31;
        float4 va = Ag[(size_t)r * 32 + c4];
        uint4 ua = make_uint4(to_tf32(va.x), to_tf32(va.y), to_tf32(va.z), to_tf32(va.w));
        *(uint4*)&As[r * STR + c4 * 4] = ua;
        float4 vb = Wg[(size_t)r * 32 + c4];
        uint4 ub = make_uint4(to_tf32(vb.x), to_tf32(vb.y), to_tf32(vb.z), to_tf32(vb.w));
        *(uint4*)&Bs[r * STR + c4 * 4] = ub;
    }
    __syncthreads();

    int warp = tid >> 5, lane = tid & 31;
    int wm = warp >> 2, wn = warp & 3;       // 2 x 4 warp grid
    int gid = lane >> 2, tg = lane & 3;

    float acc[4][4][4];
    #pragma unroll
    for (int i = 0; i < 4; i++)
        #pragma unroll
        for (int j = 0; j < 4; j++)
            #pragma unroll
            for (int c = 0; c < 4; c++) acc[i][j][c] = 0.f;

    #pragma unroll
    for (int ks = 0; ks < 16; ks++) {
        int k0 = ks * 8 + tg;
        unsigned a[4][4], bf[4][2];
        #pragma unroll
        for (int i = 0; i < 4; i++) {
            int r0 = wm * 64 + i * 16 + gid;
            a[i][0] = As[r0 * STR + k0];
            a[i][1] = As[(r0 + 8) * STR + k0];
            a[i][2] = As[r0 * STR + k0 + 4];
            a[i][3] = As[(r0 + 8) * STR + k0 + 4];
        }
        #pragma unroll
        for (int j = 0; j < 4; j++) {
            int n0 = wn * 32 + j * 8 + gid;
            bf[j][0] = Bs[n0 * STR + k0];
            bf[j][1] = Bs[n0 * STR + k0 + 4];
        }
        #pragma unroll
        for (int i = 0; i < 4; i++)
            #pragma unroll
            for (int j = 0; j < 4; j++)
                asm volatile(
                    "mma.sync.aligned.m16n8k8.row.col.f32.tf32.tf32.f32 "
                    "{%0,%1,%2,%3}, {%4,%5,%6,%7}, {%8,%9}, {%0,%1,%2,%3};"
                    : "+f"(acc[i][j][0]), "+f"(acc[i][j][1]),
                      "+f"(acc[i][j][2]), "+f"(acc[i][j][3])
                    : "r"(a[i][0]), "r"(a[i][1]), "r"(a[i][2]), "r"(a[i][3]),
                      "r"(bf[j][0]), "r"(bf[j][1]));
    }

    // epilogue: row r = b*128 + l  ->  pre[(l*512 + b)*512 + col], + bias
    #pragma unroll
    for (int i = 0; i < 4; i++) {
        int r0 = bm * 128 + wm * 64 + i * 16 + gid;
        int ra = r0, rb = r0 + 8;
        float* outa = g_pre + ((size_t)(ra & 127) * 512 + (ra >> 7)) * 512;
        float* outb = g_pre + ((size_t)(rb & 127) * 512 + (rb >> 7)) * 512;
        #pragma unroll
        for (int j = 0; j < 4; j++) {
            int col = bn * 128 + wn * 32 + j * 8 + tg * 2;
            float bz0 = __ldg(&bias[col]);
            float bz1 = __ldg(&bias[col + 1]);
            *(float2*)&outa[col] = make_float2(acc[i][j][0] + bz0, acc[i][j][1] + bz1);
            *(float2*)&outb[col] = make_float2(acc[i][j][2] + bz0, acc[i][j][3] + bz1);
        }
    }
}

// ---------------------------------------------------------------------------
// sLSTM gate math (scalar, fp32, fast-intrinsic transcendentals)
// ---------------------------------------------------------------------------
__device__ __forceinline__ void gate_step(float ai, float af, float az, float ao,
                                          float& h, float& c, float& n, float& m) {
    float mn = fmaxf(af + m, ai);
    float iv = __expf(ai - mn);
    float fv = __expf(af + m - mn);
    float zc = fminf(fmaxf(az, -15.f), 15.f);
    float e2 = __expf(2.f * zc);
    float th = __fdividef(e2 - 1.f, e2 + 1.f);
    c = fv * c + iv * th;
    n = fv * n + iv;
    float sg = __fdividef(1.f, 1.f + __expf(-ao));
    h = sg * __fdividef(c, n);
    m = mn;
}

// ---------------------------------------------------------------------------
// Recurrent sLSTM scan + fused GroupNorm + residual into g_x.
// Grid 128 CTAs x 256 threads = 1 clean wave on 148 SMs.
// Each CTA handles 4 batches; each THREAD handles 2 batches (ILP=2) for one
// output dim o (warp = head). Rr held as 64 x b64 register pairs shared by
// both batches; matvec via fma.rn.f32x2 over adjacent-d pairs.
// No barriers inside the 128-step loop.
// ---------------------------------------------------------------------------
__global__ void __launch_bounds__(256, 1) k_scan(const float* __restrict__ R,
                                                 const float* __restrict__ gnw) {
    const unsigned FULL = 0xffffffffu;
    int o    = threadIdx.x & 127;            // output dim
    int grp  = threadIdx.x >> 7;             // which pair of batches
    int hh   = (threadIdx.x >> 5) & 3;       // head
    int lane = threadIdx.x & 31;

    int b0 = blockIdx.x * 4 + grp * 2;       // batch A; batch B = b0+1

    // Rr2[g*16+dp] = ( R[g][hh][2dp][lane], R[g][hh][2dp+1][lane] )
    ull Rr2[64];
    #pragma unroll
    for (int g = 0; g < 4; g++)
        #pragma unroll
        for (int dp = 0; dp < 16; dp++) {
            float r0 = __ldg(&R[((g * 4 + hh) * 32 + 2 * dp)     * 32 + lane]);
            float r1 = __ldg(&R[((g * 4 + hh) * 32 + 2 * dp + 1) * 32 + lane]);
            Rr2[g * 16 + dp] = pack2(r0, r1);
        }

    float gw = __ldg(&gnw[o]);

    float hA = 0.f, cA = 0.f, nA = 0.f, mA = 0.f;
    float hB = 0.f, cB = 0.f, nB = 0.f, mB = 0.f;

    const float* pA = g_pre + (size_t)b0 * 512 + o;
    const float* pB = pA + 512;
    float* xA = g_x + (size_t)b0 * kL * kD + o;
    float* xB = xA + (size_t)kL * kD;

    // prefetch step 0
    float a0 = pA[0], a1 = pA[128], a2 = pA[256], a3 = pA[384];
    float q0 = pB[0], q1 = pB[128], q2 = pB[256], q3 = pB[384];

    for (int t = 0; t < kL; t++) {
        // accumulators carry the preactivation in the low half
        ull aiA = pack2(a0, 0.f), afA = pack2(a1, 0.f);
        ull azA = pack2(a2, 0.f), aoA = pack2(a3, 0.f);
        ull aiB = pack2(q0, 0.f), afB = pack2(q1, 0.f);
        ull azB = pack2(q2, 0.f), aoB = pack2(q3, 0.f);

        if (t + 1 < kL) {
            const float* nA_ = pA + (size_t)(t + 1) * (kB * 512);
            const float* nB_ = pB + (size_t)(t + 1) * (kB * 512);
            a0 = nA_[0]; a1 = nA_[128]; a2 = nA_[256]; a3 = nA_[384];
            q0 = nB_[0]; q1 = nB_[128]; q2 = nB_[256]; q3 = nB_[384];
        }

        // recurrent mix: within-head matvec, f32x2 over adjacent-d pairs
        #pragma unroll
        for (int dp = 0; dp < 16; dp++) {
            float hA0 = __shfl_sync(FULL, hA, 2 * dp);
            float hA1 = __shfl_sync(FULL, hA, 2 * dp + 1);
            ull hpA = pack2(hA0, hA1);
            float hB0 = __shfl_sync(FULL, hB, 2 * dp);
            float hB1 = __shfl_sync(FULL, hB, 2 * dp + 1);
            ull hpB = pack2(hB0, hB1);
            aiA = ffma2(hpA, Rr2[dp],      aiA);
            afA = ffma2(hpA, Rr2[16 + dp], afA);
            azA = ffma2(hpA, Rr2[32 + dp], azA);
            aoA = ffma2(hpA, Rr2[48 + dp], aoA);
            aiB = ffma2(hpB, Rr2[dp],      aiB);
            afB = ffma2(hpB, Rr2[16 + dp], afB);
            azB = ffma2(hpB, Rr2[32 + dp], azB);
            aoB = ffma2(hpB, Rr2[48 + dp], aoB);
        }

        float lo, hi;
        unpack2(aiA, lo, hi); float gAi = lo + hi;
        unpack2(afA, lo, hi); float gAf = lo + hi;
        unpack2(azA, lo, hi); float gAz = lo + hi;
        unpack2(aoA, lo, hi); float gAo = lo + hi;
        unpack2(aiB, lo, hi); float gBi = lo + hi;
        unpack2(afB, lo, hi); float gBf = lo + hi;
        unpack2(azB, lo, hi); float gBz = lo + hi;
        unpack2(aoB, lo, hi); float gBo = lo + hi;

        gate_step(gAi, gAf, gAz, gAo, hA, cA, nA, mA);
        gate_step(gBi, gBf, gBz, gBo, hB, cB, nB, mB);

        // fused GroupNorm over the head (this warp) + residual into g_x
        // pack (sum, sumsq) per batch; 64-bit shfl = 2x shfl.b32
        ull rA = pack2(hA, hA * hA);
        ull rB = pack2(hB, hB * hB);
        #pragma unroll
        for (int off = 16; off; off >>= 1) {
            rA = add2(rA, __shfl_xor_sync(FULL, rA, off));
            rB = add2(rB, __shfl_xor_sync(FULL, rB, off));
        }
        float sA, qA2; unpack2(rA, sA, qA2);
        float sB, qB2; unpack2(rB, sB, qB2);
        {
            float mu  = sA * (1.f / 32.f);
            float var = fmaxf(qA2 * (1.f / 32.f) - mu * mu, 0.f);
            float y   = (hA - mu) * rsqrtf(var + 1e-5f) * gw;
            xA[(size_t)t * kD] += y;
        }
        {
            float mu  = sB * (1.f / 32.f);
            float var = fmaxf(qB2 * (1.f / 32.f) - mu * mu, 0.f);
            float y   = (hB - mu) * rsqrtf(var + 1e-5f) * gw;
            xB[(size_t)t * kD] += y;
        }
    }
}

// ---------------------------------------------------------------------------
// Head: mean over time, then 128->64 ReLU MLP, then 64->2
// ---------------------------------------------------------------------------
__global__ void k_head(const float* __restrict__ w1, const float* __restrict__ b1,
                       const float* __restrict__ w2, const float* __restrict__ b2,
                       float* __restrict__ out) {
    __shared__ float pooled[128];
    __shared__ float hid[64];
    int b = blockIdx.x, o = threadIdx.x;
    const float* xb = g_x + (size_t)b * kL * kD + o;
    float s = 0.f;
    #pragma unroll 8
    for (int t = 0; t < kL; t++) s += xb[(size_t)t * kD];
    pooled[o] = s * (1.f / 128.f);
    __syncthreads();
    if (o < 64) {
        float a = __ldg(&b1[o]);
        const float* wr = w1 + o * 128;
        #pragma unroll
        for (int d = 0; d < 128; d++) a = fmaf(pooled[d], __ldg(&wr[d]), a);
        hid[o] = fmaxf(a, 0.f);
    }
    __syncthreads();
    if (o < 2) {
        float a = __ldg(&b2[o]);
        const float* wr = w2 + o * 64;
        #pragma unroll
        for (int j = 0; j < 64; j++) a = fmaf(hid[j], __ldg(&wr[j]), a);
        out[b * 2 + o] = a;
    }
}

// ---------------------------------------------------------------------------
extern "C" void kernel_launch(void* const* d_in, const int* in_sizes, int n_in,
                              void* d_out, int out_size) {
    const int*   ids  = (const int*)  d_in[0];
    const float* emb  = (const float*)d_in[1];
    const float* ln_w = (const float*)d_in[2];
    const float* ln_b = (const float*)d_in[3];
    const float* Wg   = (const float*)d_in[4];
    const float* Rg   = (const float*)d_in[5];
    const float* bg   = (const float*)d_in[6];
    const float* gn_w = (const float*)d_in[7];
    const float* w1   = (const float*)d_in[8];
    const float* b1   = (const float*)d_in[9];
    const float* w2   = (const float*)d_in[10];
    const float* b2   = (const float*)d_in[11];
    float* out = (float*)d_out;

    constexpr int GEMM_SMEM = 2 * 128 * 132 * 4;   // 135168 B
    cudaFuncSetAttribute(k_gemm, cudaFuncAttributeMaxDynamicSharedMemorySize, GEMM_SMEM);

    k_embed<<<(kB * kL * 32 + 255) / 256, 256>>>(ids, (const float4*)emb);
    for (int l = 0; l < 2; l++) {
        k_ln<<<kB * kL / 8, 256>>>(ln_w + l * 128, ln_b + l * 128);
        k_gemm<<<dim3(512, 4), 256, GEMM_SMEM>>>(Wg + (size_t)l * 4 * 128 * 128,
                                                 bg + l * 512);
        k_scan<<<128, 256>>>(Rg + (size_t)l * 4 * 4 * 32 * 32, gn_w + l * 128);
    }
    k_head<<<512, 128>>>(w1, b1, w2, b2, out);
}

// round 3
// speedup vs baseline: 1.5482x; 1.1621x over previous
#include <cuda_runtime.h>

// Problem constants
constexpr int kB = 512;   // batch
constexpr int kL = 128;   // seq len
constexpr int kD = 128;   // model dim
// H = 4 heads of 32

// Scratch (device globals: allocation-free rule)
__device__ float g_x [kB * kL * kD];                 // residual stream, [b][t][d]   (32 MB)
__device__ float g_xn[kB * kL * kD];                 // layernormed,    [b*L+l][d]   (32 MB)
__device__ float g_h [kB * kL * kD];                 // raw scan output h            (32 MB)
__device__ float g_pre[(size_t)kL * kB * 4 * kD];    // gate preacts,   [t][b][g][d] (128 MB)

typedef unsigned long long ull;

__device__ __forceinline__ ull pack2(float lo, float hi) {
    ull r; asm("mov.b64 %0,{%1,%2};" : "=l"(r) : "f"(lo), "f"(hi)); return r;
}
__device__ __forceinline__ void unpack2(ull v, float& lo, float& hi) {
    asm("mov.b64 {%0,%1},%2;" : "=f"(lo), "=f"(hi) : "l"(v));
}
__device__ __forceinline__ ull ffma2(ull a, ull b, ull c) {
    ull d; asm("fma.rn.f32x2 %0,%1,%2,%3;" : "=l"(d) : "l"(a), "l"(b), "l"(c)); return d;
}
__device__ __forceinline__ float tanh_fast(float x) {
    float y; asm("tanh.approx.f32 %0,%1;" : "=f"(y) : "f"(x)); return y;
}

// ---------------------------------------------------------------------------
// Embedding gather: g_x[b,l,:] = emb[ids[b,l], :]
// ---------------------------------------------------------------------------
__global__ void k_embed(const int* __restrict__ ids, const float4* __restrict__ emb) {
    int tid = blockIdx.x * 256 + threadIdx.x;          // one float4 per thread
    if (tid >= kB * kL * 32) return;
    int row = tid >> 5;                                 // (b*L + l)
    int c4  = tid & 31;
    int id  = __ldg(&ids[row]);
    ((float4*)g_x)[tid] = emb[(size_t)id * 32 + c4];
}

// ---------------------------------------------------------------------------
// LayerNorm (layer 0 only): one warp per row of 128
// ---------------------------------------------------------------------------
__global__ void k_ln(const float* __restrict__ w, const float* __restrict__ bb) {
    int t    = blockIdx.x * 256 + threadIdx.x;
    int warp = t >> 5;
    int lane = t & 31;
    float4 v = ((const float4*)g_x)[(size_t)warp * 32 + lane];
    float s = v.x + v.y + v.z + v.w;
    float q = v.x*v.x + v.y*v.y + v.z*v.z + v.w*v.w;
    #pragma unroll
    for (int o = 16; o; o >>= 1) {
        s += __shfl_xor_sync(0xffffffffu, s, o);
        q += __shfl_xor_sync(0xffffffffu, q, o);
    }
    float mu  = s * (1.f / 128.f);
    float var = fmaxf(q * (1.f / 128.f) - mu * mu, 0.f);
    float rs  = rsqrtf(var + 1e-5f);
    float4 wv = ((const float4*)w)[lane];
    float4 bv = ((const float4*)bb)[lane];
    float4 o4;
    o4.x = (v.x - mu) * rs * wv.x + bv.x;
    o4.y = (v.y - mu) * rs * wv.y + bv.y;
    o4.z = (v.z - mu) * rs * wv.z + bv.z;
    o4.w = (v.w - mu) * rs * wv.w + bv.w;
    ((float4*)g_xn)[(size_t)warp * 32 + lane] = o4;
}

// ---------------------------------------------------------------------------
// Fused GroupNorm + residual (+ optional LayerNorm for the next layer).
// x' = x + GN_head(h) ; g_x = x' ; if DO_LN: g_xn = LN(x').
// One warp per row of 128; head = 8-lane subgroup (8 lanes x float4 = 32).
// ---------------------------------------------------------------------------
template<bool DO_LN>
__global__ void k_gn(const float* __restrict__ gnw,
                     const float* __restrict__ lnw, const float* __restrict__ lnb) {
    const unsigned FULL = 0xffffffffu;
    int t    = blockIdx.x * 256 + threadIdx.x;
    int row  = t >> 5;
    int lane = t & 31;
    float4 hv = ((const float4*)g_h)[(size_t)row * 32 + lane];
    float4 xv = ((const float4*)g_x)[(size_t)row * 32 + lane];
    float s = hv.x + hv.y + hv.z + hv.w;
    float q = hv.x*hv.x + hv.y*hv.y + hv.z*hv.z + hv.w*hv.w;
    #pragma unroll
    for (int o = 1; o < 8; o <<= 1) {         // reduce within 8-lane head group
        s += __shfl_xor_sync(FULL, s, o);
        q += __shfl_xor_sync(FULL, q, o);
    }
    float mu  = s * (1.f / 32.f);
    float var = fmaxf(q * (1.f / 32.f) - mu * mu, 0.f);
    float rs  = rsqrtf(var + 1e-5f);
    float4 gw = ((const float4*)gnw)[lane];
    float4 xp;
    xp.x = xv.x + (hv.x - mu) * rs * gw.x;
    xp.y = xv.y + (hv.y - mu) * rs * gw.y;
    xp.z = xv.z + (hv.z - mu) * rs * gw.z;
    xp.w = xv.w + (hv.w - mu) * rs * gw.w;
    ((float4*)g_x)[(size_t)row * 32 + lane] = xp;

    if (DO_LN) {
        float s2 = xp.x + xp.y + xp.z + xp.w;
        float q2 = xp.x*xp.x + xp.y*xp.y + xp.z*xp.z + xp.w*xp.w;
        #pragma unroll
        for (int o = 16; o; o >>= 1) {
            s2 += __shfl_xor_sync(FULL, s2, o);
            q2 += __shfl_xor_sync(FULL, q2, o);
        }
        float mu2  = s2 * (1.f / 128.f);
        float var2 = fmaxf(q2 * (1.f / 128.f) - mu2 * mu2, 0.f);
        float rs2  = rsqrtf(var2 + 1e-5f);
        float4 wv = ((const float4*)lnw)[lane];
        float4 bv = ((const float4*)lnb)[lane];
        float4 o4;
        o4.x = (xp.x - mu2) * rs2 * wv.x + bv.x;
        o4.y = (xp.y - mu2) * rs2 * wv.y + bv.y;
        o4.z = (xp.z - mu2) * rs2 * wv.z + bv.z;
        o4.w = (xp.w - mu2) * rs2 * wv.w + bv.w;
        ((float4*)g_xn)[(size_t)row * 32 + lane] = o4;
    }
}

// ---------------------------------------------------------------------------
// tf32 GEMM: pre[l,b,g*128+o] = xn[b*L+l, :] . W[g*128+o, :] + bias
// ---------------------------------------------------------------------------
__device__ __forceinline__ unsigned to_tf32(float f) {
    unsigned u;
    asm("cvt.rna.tf32.f32 %0, %1;" : "=r"(u) : "f"(f));
    return u;
}

__global__ void __launch_bounds__(256) k_gemm(const float* __restrict__ W,
                                              const float* __restrict__ bias) {
    constexpr int STR = 132;                 // padded smem stride (floats)
    extern __shared__ unsigned sh[];
    unsigned* As = sh;                       // [128][132] tf32 of xn tile
    unsigned* Bs = sh + 128 * STR;           // [128][132] tf32 of W tile

    int tid = threadIdx.x;
    int bm  = blockIdx.x;                    // row tile (== batch index b)
    int bn  = blockIdx.y;                    // col tile (== gate g)

    const float4* Ag = ((const float4*)g_xn) + (size_t)bm * 128 * 32;
    const float4* Wg = ((const float4*)W)    + (size_t)bn * 128 * 32;

    #pragma unroll
    for (int i = 0; i < 16; i++) {
        int e  = i * 256 + tid;
        int r  = e >> 5, c4 = e & 31;
        float4 va = Ag[(size_t)r * 32 + c4];
        uint4 ua = make_uint4(to_tf32(va.x), to_tf32(va.y), to_tf32(va.z), to_tf32(va.w));
        *(uint4*)&As[r * STR + c4 * 4] = ua;
        float4 vb = Wg[(size_t)r * 32 + c4];
        uint4 ub = make_uint4(to_tf32(vb.x), to_tf32(vb.y), to_tf32(vb.z), to_tf32(vb.w));
        *(uint4*)&Bs[r * STR + c4 * 4] = ub;
    }
    __syncthreads();

    int warp = tid >> 5, lane = tid & 31;
    int wm = warp >> 2, wn = warp & 3;
    int gid = lane >> 2, tg = lane & 3;

    float acc[4][4][4];
    #pragma unroll
    for (int i = 0; i < 4; i++)
        #pragma unroll
        for (int j = 0; j < 4; j++)
            #pragma unroll
            for (int c = 0; c < 4; c++) acc[i][j][c] = 0.f;

    #pragma unroll
    for (int ks = 0; ks < 16; ks++) {
        int k0 = ks * 8 + tg;
        unsigned a[4][4], bf[4][2];
        #pragma unroll
        for (int i = 0; i < 4; i++) {
            int r0 = wm * 64 + i * 16 + gid;
            a[i][0] = As[r0 * STR + k0];
            a[i][1] = As[(r0 + 8) * STR + k0];
            a[i][2] = As[r0 * STR + k0 + 4];
            a[i][3] = As[(r0 + 8) * STR + k0 + 4];
        }
        #pragma unroll
        for (int j = 0; j < 4; j++) {
            int n0 = wn * 32 + j * 8 + gid;
            bf[j][0] = Bs[n0 * STR + k0];
            bf[j][1] = Bs[n0 * STR + k0 + 4];
        }
        #pragma unroll
        for (int i = 0; i < 4; i++)
            #pragma unroll
            for (int j = 0; j < 4; j++)
                asm volatile(
                    "mma.sync.aligned.m16n8k8.row.col.f32.tf32.tf32.f32 "
                    "{%0,%1,%2,%3}, {%4,%5,%6,%7}, {%8,%9}, {%0,%1,%2,%3};"
                    : "+f"(acc[i][j][0]), "+f"(acc[i][j][1]),
                      "+f"(acc[i][j][2]), "+f"(acc[i][j][3])
                    : "r"(a[i][0]), "r"(a[i][1]), "r"(a[i][2]), "r"(a[i][3]),
                      "r"(bf[j][0]), "r"(bf[j][1]));
    }

    // epilogue: row r = b*128 + l  ->  pre[(l*512 + b)*512 + col], + bias
    #pragma unroll
    for (int i = 0; i < 4; i++) {
        int r0 = bm * 128 + wm * 64 + i * 16 + gid;
        int ra = r0, rb = r0 + 8;
        float* outa = g_pre + ((size_t)(ra & 127) * 512 + (ra >> 7)) * 512;
        float* outb = g_pre + ((size_t)(rb & 127) * 512 + (rb >> 7)) * 512;
        #pragma unroll
        for (int j = 0; j < 4; j++) {
            int col = bn * 128 + wn * 32 + j * 8 + tg * 2;
            float bz0 = __ldg(&bias[col]);
            float bz1 = __ldg(&bias[col + 1]);
            *(float2*)&outa[col] = make_float2(acc[i][j][0] + bz0, acc[i][j][1] + bz1);
            *(float2*)&outb[col] = make_float2(acc[i][j][2] + bz0, acc[i][j][3] + bz1);
        }
    }
}

// ---------------------------------------------------------------------------
// sLSTM gate math: 5 MUFU total (3 ex2 + tanh + rcp)
// ---------------------------------------------------------------------------
__device__ __forceinline__ void gate_step(float ai, float af, float az, float ao,
                                          float& h, float& c, float& n, float& m) {
    float fm = af + m;
    float mn = fmaxf(fm, ai);
    float iv = __expf(ai - mn);
    float fv = __expf(fm - mn);
    float th = tanh_fast(az);
    c = fmaf(fv, c, iv * th);
    n = fmaf(fv, n, iv);
    float eo = __expf(-ao);                   // h = sigmoid(ao) * c / n
    float denom = fmaf(n, eo, n);             //   = c / (n * (1 + e^-ao))
    h = __fdividef(c, denom);
    m = mn;
}

// ---------------------------------------------------------------------------
// Recurrent sLSTM scan. Grid 128 x 256. Thread = (batch-pair, dim o); warp =
// head. h broadcast through SMEM (8 LDS.128/batch) instead of shuffles.
// GroupNorm deferred to k_gn; raw h written to g_h.
// ---------------------------------------------------------------------------
__global__ void __launch_bounds__(256, 1) k_scan(const float* __restrict__ R,
                                                 const float* __restrict__ bias_unused) {
    __shared__ float shA[2][2][4][32];        // [slot][grp][head][d]
    __shared__ float shB[2][2][4][32];

    int o    = threadIdx.x & 127;            // output dim
    int grp  = threadIdx.x >> 7;             // batch pair within CTA
    int hh   = (threadIdx.x >> 5) & 3;       // head
    int lane = threadIdx.x & 31;

    int b0 = blockIdx.x * 4 + grp * 2;       // batch A; batch B = b0+1

    // Rr2[g*16+dp] = ( R[g][hh][2dp][lane], R[g][hh][2dp+1][lane] )
    ull Rr2[64];
    #pragma unroll
    for (int g = 0; g < 4; g++)
        #pragma unroll
        for (int dp = 0; dp < 16; dp++) {
            float r0 = __ldg(&R[((g * 4 + hh) * 32 + 2 * dp)     * 32 + lane]);
            float r1 = __ldg(&R[((g * 4 + hh) * 32 + 2 * dp + 1) * 32 + lane]);
            Rr2[g * 16 + dp] = pack2(r0, r1);
        }

    float hA = 0.f, cA = 0.f, nA = 0.f, mA = 0.f;
    float hB = 0.f, cB = 0.f, nB = 0.f, mB = 0.f;

    const float* pA = g_pre + (size_t)b0 * 512 + o;
    const float* pB = pA + 512;
    float* hoA = g_h + (size_t)b0 * kL * kD + o;
    float* hoB = hoA + (size_t)kL * kD;

    // prefetch step 0
    float a0 = pA[0], a1 = pA[128], a2 = pA[256], a3 = pA[384];
    float q0 = pB[0], q1 = pB[128], q2 = pB[256], q3 = pB[384];

    for (int t = 0; t < kL; t++) {
        int s = t & 1;
        shA[s][grp][hh][lane] = hA;
        shB[s][grp][hh][lane] = hB;
        __syncwarp();

        ull aiA = pack2(a0, 0.f), afA = pack2(a1, 0.f);
        ull azA = pack2(a2, 0.f), aoA = pack2(a3, 0.f);
        ull aiB = pack2(q0, 0.f), afB = pack2(q1, 0.f);
        ull azB = pack2(q2, 0.f), aoB = pack2(q3, 0.f);

        if (t + 1 < kL) {
            const float* nA_ = pA + (size_t)(t + 1) * (kB * 512);
            const float* nB_ = pB + (size_t)(t + 1) * (kB * 512);
            a0 = nA_[0]; a1 = nA_[128]; a2 = nA_[256]; a3 = nA_[384];
            q0 = nB_[0]; q1 = nB_[128]; q2 = nB_[256]; q3 = nB_[384];
        }

        // recurrent mix: h via SMEM broadcast, fma.rn.f32x2 over adjacent-d pairs
        const float4* h4A = (const float4*)shA[s][grp][hh];
        const float4* h4B = (const float4*)shB[s][grp][hh];
        #pragma unroll
        for (int j = 0; j < 8; j++) {
            float4 va = h4A[j];
            float4 vb = h4B[j];
            ull a01 = pack2(va.x, va.y), a23 = pack2(va.z, va.w);
            ull b01 = pack2(vb.x, vb.y), b23 = pack2(vb.z, vb.w);
            int dp = 2 * j;
            aiA = ffma2(a01, Rr2[dp],      aiA); aiA = ffma2(a23, Rr2[dp + 1],      aiA);
            afA = ffma2(a01, Rr2[16 + dp], afA); afA = ffma2(a23, Rr2[16 + dp + 1], afA);
            azA = ffma2(a01, Rr2[32 + dp], azA); azA = ffma2(a23, Rr2[32 + dp + 1], azA);
            aoA = ffma2(a01, Rr2[48 + dp], aoA); aoA = ffma2(a23, Rr2[48 + dp + 1], aoA);
            aiB = ffma2(b01, Rr2[dp],      aiB); aiB = ffma2(b23, Rr2[dp + 1],      aiB);
            afB = ffma2(b01, Rr2[16 + dp], afB); afB = ffma2(b23, Rr2[16 + dp + 1], afB);
            azB = ffma2(b01, Rr2[32 + dp], azB); azB = ffma2(b23, Rr2[32 + dp + 1], azB);
            aoB = ffma2(b01, Rr2[48 + dp], aoB); aoB = ffma2(b23, Rr2[48 + dp + 1], aoB);
        }

        float lo, hi;
        unpack2(aiA, lo, hi); float gAi = lo + hi;
        unpack2(afA, lo, hi); float gAf = lo + hi;
        unpack2(azA, lo, hi); float gAz = lo + hi;
        unpack2(aoA, lo, hi); float gAo = lo + hi;
        unpack2(aiB, lo, hi); float gBi = lo + hi;
        unpack2(afB, lo, hi); float gBf = lo + hi;
        unpack2(azB, lo, hi); float gBz = lo + hi;
        unpack2(aoB, lo, hi); float gBo = lo + hi;

        gate_step(gAi, gAf, gAz, gAo, hA, cA, nA, mA);
        gate_step(gBi, gBf, gBz, gBo, hB, cB, nB, mB);

        hoA[(size_t)t * kD] = hA;
        hoB[(size_t)t * kD] = hB;
    }
}

// ---------------------------------------------------------------------------
// Head: mean over time, then 128->64 ReLU MLP, then 64->2
// ---------------------------------------------------------------------------
__global__ void k_head(const float* __restrict__ w1, const float* __restrict__ b1,
                       const float* __restrict__ w2, const float* __restrict__ b2,
                       float* __restrict__ out) {
    __shared__ float pooled[128];
    __shared__ float hid[64];
    int b = blockIdx.x, o = threadIdx.x;
    const float* xb = g_x + (size_t)b * kL * kD + o;
    float s = 0.f;
    #pragma unroll 8
    for (int t = 0; t < kL; t++) s += xb[(size_t)t * kD];
    pooled[o] = s * (1.f / 128.f);
    __syncthreads();
    if (o < 64) {
        float a = __ldg(&b1[o]);
        const float* wr = w1 + o * 128;
        #pragma unroll
        for (int d = 0; d < 128; d++) a = fmaf(pooled[d], __ldg(&wr[d]), a);
        hid[o] = fmaxf(a, 0.f);
    }
    __syncthreads();
    if (o < 2) {
        float a = __ldg(&b2[o]);
        const float* wr = w2 + o * 64;
        #pragma unroll
        for (int j = 0; j < 64; j++) a = fmaf(hid[j], __ldg(&wr[j]), a);
        out[b * 2 + o] = a;
    }
}

// ---------------------------------------------------------------------------
extern "C" void kernel_launch(void* const* d_in, const int* in_sizes, int n_in,
                              void* d_out, int out_size) {
    const int*   ids  = (const int*)  d_in[0];
    const float* emb  = (const float*)d_in[1];
    const float* ln_w = (const float*)d_in[2];
    const float* ln_b = (const float*)d_in[3];
    const float* Wg   = (const float*)d_in[4];
    const float* Rg   = (const float*)d_in[5];
    const float* bg   = (const float*)d_in[6];
    const float* gn_w = (const float*)d_in[7];
    const float* w1   = (const float*)d_in[8];
    const float* b1   = (const float*)d_in[9];
    const float* w2   = (const float*)d_in[10];
    const float* b2   = (const float*)d_in[11];
    float* out = (float*)d_out;

    constexpr int GEMM_SMEM = 2 * 128 * 132 * 4;   // 135168 B
    cudaFuncSetAttribute(k_gemm, cudaFuncAttributeMaxDynamicSharedMemorySize, GEMM_SMEM);

    const int ROWS = kB * kL;                      // 65536 rows of 128

    k_embed<<<(ROWS * 32 + 255) / 256, 256>>>(ids, (const float4*)emb);

    // layer 0
    k_ln<<<ROWS / 8, 256>>>(ln_w, ln_b);
    k_gemm<<<dim3(512, 4), 256, GEMM_SMEM>>>(Wg, bg);
    k_scan<<<128, 256>>>(Rg, nullptr);
    k_gn<true><<<ROWS / 8, 256>>>(gn_w, ln_w + 128, ln_b + 128);   // GN + residual + LN(l1)

    // layer 1
    k_gemm<<<dim3(512, 4), 256, GEMM_SMEM>>>(Wg + (size_t)4 * 128 * 128, bg + 512);
    k_scan<<<128, 256>>>(Rg + (size_t)4 * 4 * 32 * 32, nullptr);
    k_gn<false><<<ROWS / 8, 256>>>(gn_w + 128, nullptr, nullptr);  // GN + residual

    k_head<<<512, 128>>>(w1, b1, w2, b2, out);
}